// round 3
// baseline (speedup 1.0000x reference)
#include <cuda_runtime.h>
#include <math.h>

constexpr int   NELEM = 8192;
constexpr int   TPB   = 128;
constexpr int   NBLK  = 256;                 // == NB; one block per bucket in phase 3
constexpr int   P1BLK = NELEM / TPB;         // 64 blocks do element work in phase 1
constexpr int   NB    = 256;                 // psi buckets
constexpr int   WB    = 13;                  // 13/256 = 0.0508 > 0.05 -> safe window radius
constexpr int   SHCAP = 1536;                // shared window capacity (float2)
constexpr float THRESH = 0.05f;
constexpr float MSEW   = 10.0f;
constexpr float LEPS   = 1e-7f;

// ---- device scratch (zero-initialized at load; self-reset every launch) ----
__device__ float2 g_sorted[NELEM];
__device__ int    g_hist[NB];
__device__ int    g_cursor[NB];
__device__ int    g_off[NB + 1];
__device__ float  g_sd[P1BLK], g_sd2[P1BLK], g_sb[P1BLK];
__device__ float  g_sinv[NBLK];
__device__ int    g_cinv[NBLK];
__device__ unsigned g_bar1_cnt, g_bar2_cnt, g_done_cnt;
__device__ unsigned g_bar1_flag, g_bar2_flag;

__device__ __forceinline__ float warp_sum_f(float v) {
    #pragma unroll
    for (int o = 16; o > 0; o >>= 1) v += __shfl_down_sync(0xffffffffu, v, o);
    return v;
}
__device__ __forceinline__ int warp_sum_i(int v) {
    #pragma unroll
    for (int o = 16; o > 0; o >>= 1) v += __shfl_down_sync(0xffffffffu, v, o);
    return v;
}
__device__ __forceinline__ double warp_sum_d(double v) {
    #pragma unroll
    for (int o = 16; o > 0; o >>= 1) v += __shfl_down_sync(0xffffffffu, v, o);
    return v;
}
__device__ __forceinline__ long long warp_sum_l(long long v) {
    #pragma unroll
    for (int o = 16; o > 0; o >>= 1) v += __shfl_down_sync(0xffffffffu, v, o);
    return v;
}

__device__ __forceinline__ float2 compute_pd(float x, float y) {
    float p = fminf(fmaxf(y, LEPS), 1.0f - LEPS);
    float l = __logf(p) - __logf(1.0f - p);
    return make_float2(y, x - l);
}

__device__ __forceinline__ void spin_on(volatile unsigned* f) {
    while (*f == 0u) { __nanosleep(32); }
}

__global__ void __launch_bounds__(TPB)
fused(const float* __restrict__ pred, const float* __restrict__ psi,
      const int* __restrict__ flag, float* __restrict__ out)
{
    const int tid = threadIdx.x;
    const int bid = blockIdx.x;

    __shared__ float  shf[3][TPB / 32];
    __shared__ int    shi[TPB / 32];
    __shared__ double shd[3][TPB / 32];
    __shared__ long long shl[TPB / 32];
    __shared__ int    sh_last;
    __shared__ float2 win[SHCAP];

    // ================= phase 1: d, moments, BCE, histogram =================
    float2 pd = make_float2(0.f, 0.f);
    int b = 0;
    const bool active = (bid < P1BLK);
    float sd = 0.f, sd2 = 0.f, sb = 0.f;
    if (active) {
        int i = bid * TPB + tid;
        float x = pred[i], y = psi[i];
        pd = compute_pd(x, y);
        b = min(NB - 1, (int)(y * (float)NB));
        atomicAdd(&g_hist[b], 1);
        sd  = pd.y;
        sd2 = pd.y * pd.y;
        sb  = fmaxf(x, 0.f) - x * y + log1pf(__expf(-fabsf(x)));
    }
    sd = warp_sum_f(sd); sd2 = warp_sum_f(sd2); sb = warp_sum_f(sb);
    if ((tid & 31) == 0) { shf[0][tid >> 5] = sd; shf[1][tid >> 5] = sd2; shf[2][tid >> 5] = sb; }
    __syncthreads();
    if (active && tid == 0) {
        float a = 0.f, c = 0.f, e = 0.f;
        #pragma unroll
        for (int w = 0; w < TPB / 32; ++w) { a += shf[0][w]; c += shf[1][w]; e += shf[2][w]; }
        g_sd[bid] = a; g_sd2[bid] = c; g_sb[bid] = e;
    }
    __threadfence();

    // ============ barrier 1 (last-arriving block does the prefix scan) ============
    if (tid == 0) sh_last = (atomicAdd(&g_bar1_cnt, 1u) == (unsigned)(NBLK - 1));
    __syncthreads();
    if (sh_last) {
        if (tid < 32) {
            int v[8]; int s = 0;
            #pragma unroll
            for (int k = 0; k < 8; ++k) { v[k] = __ldcg(&g_hist[tid * 8 + k]); s += v[k]; }
            int excl = s;
            #pragma unroll
            for (int o = 1; o < 32; o <<= 1) {
                int t = __shfl_up_sync(0xffffffffu, excl, o);
                if (tid >= o) excl += t;
            }
            excl -= s;
            int run = excl;
            #pragma unroll
            for (int k = 0; k < 8; ++k) { g_off[tid * 8 + k] = run; run += v[k]; }
            if (tid == 31) g_off[NB] = run;
        }
        __syncthreads();
        __threadfence();
        if (tid == 0) atomicExch(&g_bar1_flag, 1u);
    } else {
        if (tid == 0) spin_on(&g_bar1_flag);
    }
    __syncthreads();

    // ================= phase 2: scatter into bucket order =================
    if (active) {
        int pos = __ldcg(&g_off[b]) + atomicAdd(&g_cursor[b], 1);
        g_sorted[pos] = pd;
    }
    __threadfence();
    if (tid == 0) sh_last = (atomicAdd(&g_bar2_cnt, 1u) == (unsigned)(NBLK - 1));
    __syncthreads();
    if (sh_last) { if (tid == 0) atomicExch(&g_bar2_flag, 1u); }
    else if (tid == 0) spin_on(&g_bar2_flag);
    __syncthreads();

    // ============ phase 3: invalid-pair scan, block bid owns bucket bid ============
    const int myb   = bid;
    const int wlo_b = max(0, myb - WB);
    const int whi_b = min(NB, myb + WB + 1);
    const int wlo = __ldcg(&g_off[wlo_b]);
    const int whi = __ldcg(&g_off[whi_b]);
    const int plo = __ldcg(&g_off[myb]);
    const int phi = __ldcg(&g_off[myb + 1]);
    const int wlen  = whi - wlo;
    const int lds_n = min(wlen, SHCAP);
    for (int k = tid; k < lds_n; k += TPB) win[k] = __ldcg(&g_sorted[wlo + k]);
    __syncthreads();

    // lanes parallelize over i within the bucket; the 4 warps split the window
    const int q    = tid >> 5;
    const int lane = tid & 31;
    const int kq0 = (wlen * q)       >> 2;
    const int kq1 = (wlen * (q + 1)) >> 2;
    const int ks1 = min(kq1, lds_n);          // shared portion
    const int kg0 = max(kq0, lds_n);          // (rare) global overflow portion

    float s_acc = 0.f; int c_acc = 0;
    for (int ii = plo + lane; ii < phi; ii += 32) {
        int io = ii - wlo;
        float2 pi = (io < lds_n) ? win[io] : __ldcg(&g_sorted[ii]);
        float yi = pi.x, di = pi.y;
        float s = 0.f; int c = 0;
        #pragma unroll 4
        for (int k = kq0; k < ks1; ++k) {
            float2 pj = win[k];                      // broadcast LDS.64
            float dp = yi - pj.x;
            if (fabsf(dp) < THRESH) { float dd = di - pj.y; s = fmaf(dd, dd, s); c++; }
        }
        for (int k = kg0; k < kq1; ++k) {            // normally empty
            float2 pj = __ldcg(&g_sorted[wlo + k]);
            float dp = yi - pj.x;
            if (fabsf(dp) < THRESH) { float dd = di - pj.y; s = fmaf(dd, dd, s); c++; }
        }
        s_acc += s; c_acc += c;
    }
    s_acc = warp_sum_f(s_acc); c_acc = warp_sum_i(c_acc);
    if ((tid & 31) == 0) { shf[0][tid >> 5] = s_acc; shi[tid >> 5] = c_acc; }
    __syncthreads();
    if (tid == 0) {
        float s = 0.f; int c = 0;
        #pragma unroll
        for (int w = 0; w < TPB / 32; ++w) { s += shf[0][w]; c += shi[w]; }
        g_sinv[bid] = s; g_cinv[bid] = c;
    }
    __threadfence();

    // ============ finalize: last-arriving block reduces everything ============
    if (tid == 0) sh_last = (atomicAdd(&g_done_cnt, 1u) == (unsigned)(NBLK - 1));
    __syncthreads();
    if (!sh_last) return;

    double ds = 0.0, ds2 = 0.0, dsb = 0.0, dsi = 0.0;
    long long ci = 0;
    for (int k = tid; k < NBLK; k += TPB) {
        dsi += (double)__ldcg(&g_sinv[k]);
        ci  += (long long)__ldcg(&g_cinv[k]);
        if (k < P1BLK) {
            ds  += (double)__ldcg(&g_sd[k]);
            ds2 += (double)__ldcg(&g_sd2[k]);
            dsb += (double)__ldcg(&g_sb[k]);
        }
    }
    ds = warp_sum_d(ds); ds2 = warp_sum_d(ds2); dsb = warp_sum_d(dsb);
    dsi = warp_sum_d(dsi); ci = warp_sum_l(ci);
    if ((tid & 31) == 0) {
        shd[0][tid >> 5] = ds; shd[1][tid >> 5] = ds2; shd[2][tid >> 5] = dsb;
        shf[0][tid >> 5] = (float)0;   // unused
        shl[tid >> 5] = ci;
    }
    __shared__ double shsi[TPB / 32];
    if ((tid & 31) == 0) shsi[tid >> 5] = dsi;
    __syncthreads();
    if (tid == 0) {
        double Sd = 0.0, Sd2 = 0.0, Sb = 0.0, Sinv = 0.0; long long Cinv = 0;
        #pragma unroll
        for (int w = 0; w < TPB / 32; ++w) {
            Sd += shd[0][w]; Sd2 += shd[1][w]; Sb += shd[2][w];
            Sinv += shsi[w]; Cinv += shl[w];
        }
        double S_all = 2.0 * (double)NELEM * Sd2 - 2.0 * Sd * Sd;
        long long Cval = (long long)NELEM * (long long)NELEM - Cinv;
        float bce = (float)(Sb / (double)NELEM);
        int bce_only = (flag != nullptr) ? *flag : 0;
        float result;
        if (bce_only) {
            result = bce;
        } else {
            double Sval = S_all - Sinv;
            if (Sval < 0.0) Sval = 0.0;
            double mse = Sval / (double)(Cval > 0 ? Cval : 1);
            result = (Cval > 0) ? (bce + MSEW * (float)mse) : bce;
        }
        out[0] = result;
    }
    // reset scratch for the next graph replay
    for (int k = tid; k < NB; k += TPB) { g_hist[k] = 0; g_cursor[k] = 0; }
    if (tid == 0) {
        g_bar1_cnt = 0u; g_bar2_cnt = 0u; g_done_cnt = 0u;
        g_bar1_flag = 0u; g_bar2_flag = 0u;
    }
}

extern "C" void kernel_launch(void* const* d_in, const int* in_sizes, int n_in,
                              void* d_out, int out_size) {
    const float* pred = (const float*)d_in[0];
    const float* psi  = (const float*)d_in[1];
    const int*   flag = (n_in >= 3 && in_sizes[2] >= 1) ? (const int*)d_in[2] : nullptr;
    fused<<<NBLK, TPB>>>(pred, psi, flag, (float*)d_out);
}